// round 5
// baseline (speedup 1.0000x reference)
#include <cuda_runtime.h>
#include <cuda_fp16.h>

#define HWSZ 262144           // 512*512
#define NB 8

// fp16 row-pair buffer for sampling: [b][x:513][y:512], 16B element =
// {c0,c1,c2,pad}(row y) ++ {c0,c1,c2,pad}(row y+1) in halves.
// Column x=512 and the row-512 half of y=511 stay ZERO (device globals are
// zero-initialized and those slots are never written) -> free OOB padding.
__device__ uint4 g_xh[NB * 513 * 512];

// ---------------------------------------------------------------------------
// packed dual-fp32 helpers (sm_103a f32x2 pipe)
// ---------------------------------------------------------------------------
__device__ __forceinline__ unsigned long long pk2(float lo, float hi) {
    unsigned long long r;
    asm("mov.b64 %0, {%1, %2};" : "=l"(r) : "f"(lo), "f"(hi));
    return r;
}
__device__ __forceinline__ void upk2(float& lo, float& hi, unsigned long long v) {
    asm("mov.b64 {%0, %1}, %2;" : "=f"(lo), "=f"(hi) : "l"(v));
}
__device__ __forceinline__ unsigned long long fma2(unsigned long long a,
                                                   unsigned long long b,
                                                   unsigned long long c) {
    unsigned long long d;
    asm("fma.rn.f32x2 %0, %1, %2, %3;" : "=l"(d) : "l"(a), "l"(b), "l"(c));
    return d;
}

// ---------------------------------------------------------------------------
// Kernel 1: build the fp16 row-pair sample buffer. grid (16,16,8), block (32,8).
// ---------------------------------------------------------------------------
__global__ __launch_bounds__(256) void k_prep(const float* __restrict__ x) {
    __shared__ float4 tile[33][33];
    int b = blockIdx.z, h0 = blockIdx.y << 5, w0 = blockIdx.x << 5;
    int tx = threadIdx.x, ty = threadIdx.y;
    const float* xb = x + (size_t)b * 3 * HWSZ;

#pragma unroll
    for (int r = 0; r < 5; r++) {
        int rr = ty + (r << 3);
        if (rr < 33) {
            int hh = h0 + rr;
            float4 v = make_float4(0.f, 0.f, 0.f, 0.f);
            if (hh < 512) {
                int hw = (hh << 9) + w0 + tx;
                v = make_float4(xb[hw], xb[HWSZ + hw], xb[2 * HWSZ + hw], 0.f);
            }
            tile[rr][tx] = v;
        }
    }
    __syncthreads();
#pragma unroll
    for (int r = 0; r < 4; r++) {
        int rr = ty + (r << 3);                 // x = w0+rr
        float4 a = tile[tx][rr];                // row y   = h0+tx
        float4 c = tile[tx + 1][rr];            // row y+1
        __half2 p0 = __floats2half2_rn(a.x, a.y);
        __half2 p1 = __floats2half2_rn(a.z, 0.f);
        __half2 p2 = __floats2half2_rn(c.x, c.y);
        __half2 p3 = __floats2half2_rn(c.z, 0.f);
        uint4 u;
        u.x = *reinterpret_cast<unsigned*>(&p0);
        u.y = *reinterpret_cast<unsigned*>(&p1);
        u.z = *reinterpret_cast<unsigned*>(&p2);
        u.w = *reinterpret_cast<unsigned*>(&p3);
        g_xh[((b * 513 + (w0 + rr)) << 9) + (h0 + tx)] = u;  // coalesced (y fast)
    }
}

// ---------------------------------------------------------------------------
// Bilinear sample: 2 scattered 16B loads. Zero padding handles OOB edges.
// ---------------------------------------------------------------------------
__device__ __forceinline__ void samp(const uint4* __restrict__ colb,
                                     float gx, float gy, float4 wv, float& acc) {
    float ix = fmaf(gx, 256.f, 255.5f);
    float iy = fmaf(gy, 256.f, 255.5f);
    if (ix >= 512.f || iy >= 512.f) return;   // only upper bound reachable
    int x0 = (int)ix, y0 = (int)iy;
    float wx1 = ix - (float)x0, wy1 = iy - (float)y0;
    float wx0 = 1.f - wx1, wy0 = 1.f - wy1;

    const uint4* c0 = colb + (x0 << 9) + y0;
    uint4 qa = __ldg(c0);          // column x0  : rows y0, y0+1
    uint4 qb = __ldg(c0 + 512);    // column x0+1 (x0=511 -> zero column)

    float2 a01  = __half22float2(*reinterpret_cast<__half2*>(&qa.x));
    float2 a2_  = __half22float2(*reinterpret_cast<__half2*>(&qa.y));
    float2 a01b = __half22float2(*reinterpret_cast<__half2*>(&qa.z));
    float2 a2b  = __half22float2(*reinterpret_cast<__half2*>(&qa.w));
    float2 b01  = __half22float2(*reinterpret_cast<__half2*>(&qb.x));
    float2 b2_  = __half22float2(*reinterpret_cast<__half2*>(&qb.y));
    float2 b01b = __half22float2(*reinterpret_cast<__half2*>(&qb.z));
    float2 b2b  = __half22float2(*reinterpret_cast<__half2*>(&qb.w));

    float cA0 = wy0 * a01.x + wy1 * a01b.x;
    float cA1 = wy0 * a01.y + wy1 * a01b.y;
    float cA2 = wy0 * a2_.x + wy1 * a2b.x;
    float cB0 = wy0 * b01.x + wy1 * b01b.x;
    float cB1 = wy0 * b01.y + wy1 * b01b.y;
    float cB2 = wy0 * b2_.x + wy1 * b2b.x;

    float s0 = wx0 * cA0 + wx1 * cB0;
    float s1 = wx0 * cA1 + wx1 * cB1;
    float s2 = wx0 * cA2 + wx1 * cB2;
    acc = fmaf(s0, wv.x, fmaf(s1, wv.y, fmaf(s2, wv.z, acc)));
}

// ---------------------------------------------------------------------------
// Kernel 2: conv3x3 (smem tile + f32x2 FMA) + sigmoid + sampling + epilogue.
// Block 128 threads = 256 px of one row (2 px/thread). grid (2, 512, 8).
// Symmetric samples k=5..8 provably OOB: ch2 = relu(b2[2]); ch1 = k3+center.
// ---------------------------------------------------------------------------
__global__ __launch_bounds__(128) void k_seesaw(const float* __restrict__ x,
                                                const float* __restrict__ w1,
                                                const float* __restrict__ b1,
                                                const float* __restrict__ w2,
                                                const float* __restrict__ b2,
                                                float* __restrict__ out) {
    __shared__ float s_tile[3][3][264];                 // [row][ch][col j], col j -> w0-1+j
    __shared__ unsigned long long s_w1p[216];           // [((ch*3+row)*3+dj)*8+o] = (w,w)
    __shared__ unsigned long long s_b1p[8];
    __shared__ float4 s_w2v[5];
    __shared__ float  s_b2[4];

    int t = threadIdx.x;
    int w0 = blockIdx.x << 8;
    int h  = blockIdx.y;
    int b  = blockIdx.z;

    // ---- weights -> smem (block is 128 threads: stride the 216 entries) ----
    for (int i = t; i < 216; i += 128) {
        int o = i & 7, r3 = i >> 3;        // r3 = (ch*3+rw)*3+dj
        int dj = r3 % 3, rw = (r3 / 3) % 3, ch = r3 / 9;
        float wv = w1[o * 27 + ch * 9 + rw * 3 + dj];
        s_w1p[i] = pk2(wv, wv);
    }
    if (t < 8) {
        s_b1p[t] = pk2(b1[t], b1[t]);
    } else if (t < 13) {
        int k = t - 8;
        s_w2v[k] = make_float4(w2[3 * k], w2[3 * k + 1], w2[3 * k + 2], 0.f);
    } else if (t < 16) {
        s_b2[t - 13] = b2[t - 13];
    }

    // ---- cooperative tile load: rows h-1..h+1, 3 channels, cols w0-1..w0+256 ----
    const float* xb = x + (size_t)b * 3 * HWSZ;
#pragma unroll
    for (int rw = 0; rw < 3; rw++) {
        int hh = h + rw - 1;
        bool vh = ((unsigned)hh < 512u);
#pragma unroll
        for (int ch = 0; ch < 3; ch++) {
            const float* src = xb + (ch << 18) + (hh << 9);
#pragma unroll
            for (int jj = 0; jj < 3; jj++) {
                int j = t + (jj << 7);
                if (j < 258) {
                    int wg = w0 - 1 + j;
                    float v = (vh && (unsigned)wg < 512u) ? __ldg(src + wg) : 0.f;
                    s_tile[rw][ch][j] = v;
                }
            }
        }
    }
    __syncthreads();

    // ---- conv3x3 for 2 pixels via packed f32x2 FMA ----
    unsigned long long zz[8];
#pragma unroll
    for (int o = 0; o < 8; o++) zz[o] = s_b1p[o];

#pragma unroll
    for (int rw = 0; rw < 3; rw++) {
#pragma unroll
        for (int ch = 0; ch < 3; ch++) {
            float2 a = *reinterpret_cast<const float2*>(&s_tile[rw][ch][2 * t]);
            float2 c = *reinterpret_cast<const float2*>(&s_tile[rw][ch][2 * t + 2]);
            unsigned long long p0 = pk2(a.x, a.y);   // tap dj=0: (px0, px1)
            unsigned long long p1 = pk2(a.y, c.x);   // tap dj=1
            unsigned long long p2 = pk2(c.x, c.y);   // tap dj=2
            int base = ((ch * 3 + rw) * 3) << 3;
#pragma unroll
            for (int o = 0; o < 8; o++) {
                zz[o] = fma2(p0, s_w1p[base + o], zz[o]);
                zz[o] = fma2(p1, s_w1p[base + 8 + o], zz[o]);
                zz[o] = fma2(p2, s_w1p[base + 16 + o], zz[o]);
            }
        }
    }

    float z0[8], z1[8];
#pragma unroll
    for (int o = 0; o < 8; o++) upk2(z0[o], z1[o], zz[o]);

    // ---- sigmoid + 5 live samples + epilogue ----
    const uint4* __restrict__ colb = g_xh + ((b * 513) << 9);
    float hb = (float)h * (1.f / 511.f);
    float vb2_0 = s_b2[0], vb2_1 = s_b2[1];
    float out2 = fmaxf(s_b2[2], 0.f);
    int w = w0 + (t << 1);

    float o0[2], o1[2];
#pragma unroll
    for (int px = 0; px < 2; px++) {
        float* z = px ? z1 : z0;
        float s[8];
#pragma unroll
        for (int o = 0; o < 8; o++)
            s[o] = __fdividef(1.f, 1.f + __expf(-z[o]));
        float wb = (float)(w + px) * (1.f / 511.f);

        float a0 = 0.f, a1 = 0.f;
        samp(colb, hb + s[0], wb + s[1], s_w2v[0], a0);   // k=0
        samp(colb, hb + s[2], wb + s[3], s_w2v[1], a0);   // k=1
        samp(colb, hb + s[4], wb + s[5], s_w2v[2], a0);   // k=2
        samp(colb, hb + s[6], wb + s[7], s_w2v[3], a1);   // k=3
        samp(colb, hb,        wb,        s_w2v[4], a1);   // k=4 center
        o0[px] = fmaxf(a0 + vb2_0, 0.f);
        o1[px] = fmaxf(a1 + vb2_1, 0.f);
    }

    int po = b * 3 * HWSZ + (h << 9) + w;
    *reinterpret_cast<float2*>(out + po)            = make_float2(o0[0], o0[1]);
    *reinterpret_cast<float2*>(out + po + HWSZ)     = make_float2(o1[0], o1[1]);
    *reinterpret_cast<float2*>(out + po + 2 * HWSZ) = make_float2(out2, out2);
}

// ---------------------------------------------------------------------------
extern "C" void kernel_launch(void* const* d_in, const int* in_sizes, int n_in,
                              void* d_out, int out_size) {
    const float* x  = (const float*)d_in[0];
    const float* w1 = (const float*)d_in[1];
    const float* b1 = (const float*)d_in[2];
    const float* w2 = (const float*)d_in[3];
    const float* b2 = (const float*)d_in[4];
    float* out = (float*)d_out;

    k_prep<<<dim3(16, 16, NB), dim3(32, 8)>>>(x);
    k_seesaw<<<dim3(2, 512, NB), 128>>>(x, w1, b1, w2, b2, out);
}

// round 6
// speedup vs baseline: 1.2505x; 1.2505x over previous
#include <cuda_runtime.h>
#include <cuda_fp16.h>

#define HWSZ 262144           // 512*512
#define NB 8

// fp16 row-pair buffer for sampling: [b][x:513][y:512], 16B element =
// {c0,c1,c2,pad}(row y) ++ {c0,c1,c2,pad}(row y+1) in halves.
// Column x=512 and the row-512 half of y=511 stay ZERO -> free OOB padding.
__device__ uint4 g_xh[NB * 513 * 512];

// ---------------------------------------------------------------------------
// packed dual-fp32 helpers (sm_103a f32x2 pipe)
// ---------------------------------------------------------------------------
__device__ __forceinline__ unsigned long long pk2(float lo, float hi) {
    unsigned long long r;
    asm("mov.b64 %0, {%1, %2};" : "=l"(r) : "f"(lo), "f"(hi));
    return r;
}
__device__ __forceinline__ void upk2(float& lo, float& hi, unsigned long long v) {
    asm("mov.b64 {%0, %1}, %2;" : "=f"(lo), "=f"(hi) : "l"(v));
}
__device__ __forceinline__ unsigned long long fma2(unsigned long long a,
                                                   unsigned long long b,
                                                   unsigned long long c) {
    unsigned long long d;
    asm("fma.rn.f32x2 %0, %1, %2, %3;" : "=l"(d) : "l"(a), "l"(b), "l"(c));
    return d;
}

// ---------------------------------------------------------------------------
// Kernel 1: build the fp16 row-pair sample buffer. grid (16,16,8), block (32,8).
// ---------------------------------------------------------------------------
__global__ __launch_bounds__(256) void k_prep(const float* __restrict__ x) {
    __shared__ float4 tile[33][33];
    int b = blockIdx.z, h0 = blockIdx.y << 5, w0 = blockIdx.x << 5;
    int tx = threadIdx.x, ty = threadIdx.y;
    const float* xb = x + (size_t)b * 3 * HWSZ;

#pragma unroll
    for (int r = 0; r < 5; r++) {
        int rr = ty + (r << 3);
        if (rr < 33) {
            int hh = h0 + rr;
            float4 v = make_float4(0.f, 0.f, 0.f, 0.f);
            if (hh < 512) {
                int hw = (hh << 9) + w0 + tx;
                v = make_float4(xb[hw], xb[HWSZ + hw], xb[2 * HWSZ + hw], 0.f);
            }
            tile[rr][tx] = v;
        }
    }
    __syncthreads();
#pragma unroll
    for (int r = 0; r < 4; r++) {
        int rr = ty + (r << 3);                 // x = w0+rr
        float4 a = tile[tx][rr];                // row y   = h0+tx
        float4 c = tile[tx + 1][rr];            // row y+1
        __half2 p0 = __floats2half2_rn(a.x, a.y);
        __half2 p1 = __floats2half2_rn(a.z, 0.f);
        __half2 p2 = __floats2half2_rn(c.x, c.y);
        __half2 p3 = __floats2half2_rn(c.z, 0.f);
        uint4 u;
        u.x = *reinterpret_cast<unsigned*>(&p0);
        u.y = *reinterpret_cast<unsigned*>(&p1);
        u.z = *reinterpret_cast<unsigned*>(&p2);
        u.w = *reinterpret_cast<unsigned*>(&p3);
        g_xh[((b * 513 + (w0 + rr)) << 9) + (h0 + tx)] = u;  // coalesced (y fast)
    }
}

// ---------------------------------------------------------------------------
// Bilinear sample: 2 scattered 16B loads. Zero padding handles OOB edges.
// ---------------------------------------------------------------------------
__device__ __forceinline__ void samp(const uint4* __restrict__ colb,
                                     float gx, float gy, float4 wv, float& acc) {
    float ix = fmaf(gx, 256.f, 255.5f);
    float iy = fmaf(gy, 256.f, 255.5f);
    if (ix >= 512.f || iy >= 512.f) return;   // only upper bound reachable
    int x0 = (int)ix, y0 = (int)iy;
    float wx1 = ix - (float)x0, wy1 = iy - (float)y0;
    float wx0 = 1.f - wx1, wy0 = 1.f - wy1;

    const uint4* c0 = colb + (x0 << 9) + y0;
    uint4 qa = __ldg(c0);          // column x0  : rows y0, y0+1
    uint4 qb = __ldg(c0 + 512);    // column x0+1 (x0=511 -> zero column)

    float2 a01  = __half22float2(*reinterpret_cast<__half2*>(&qa.x));
    float2 a2_  = __half22float2(*reinterpret_cast<__half2*>(&qa.y));
    float2 a01b = __half22float2(*reinterpret_cast<__half2*>(&qa.z));
    float2 a2b  = __half22float2(*reinterpret_cast<__half2*>(&qa.w));
    float2 b01  = __half22float2(*reinterpret_cast<__half2*>(&qb.x));
    float2 b2_  = __half22float2(*reinterpret_cast<__half2*>(&qb.y));
    float2 b01b = __half22float2(*reinterpret_cast<__half2*>(&qb.z));
    float2 b2b  = __half22float2(*reinterpret_cast<__half2*>(&qb.w));

    float cA0 = wy0 * a01.x + wy1 * a01b.x;
    float cA1 = wy0 * a01.y + wy1 * a01b.y;
    float cA2 = wy0 * a2_.x + wy1 * a2b.x;
    float cB0 = wy0 * b01.x + wy1 * b01b.x;
    float cB1 = wy0 * b01.y + wy1 * b01b.y;
    float cB2 = wy0 * b2_.x + wy1 * b2b.x;

    float s0 = wx0 * cA0 + wx1 * cB0;
    float s1 = wx0 * cA1 + wx1 * cB1;
    float s2 = wx0 * cA2 + wx1 * cB2;
    acc = fmaf(s0, wv.x, fmaf(s1, wv.y, fmaf(s2, wv.z, acc)));
}

// ---------------------------------------------------------------------------
// Kernel 2: conv3x3 (smem tile; f32x2 packed over OUTPUT-CHANNEL pairs so
// weights load as vectors) + sigmoid + sampling + epilogue.
// Block 128 threads = 256 px of one row (2 px/thread). grid (2, 512, 8).
// Symmetric samples k=5..8 provably OOB: ch2 = relu(b2[2]); ch1 = k3+center.
// ---------------------------------------------------------------------------
__global__ __launch_bounds__(128) void k_seesaw(const float* __restrict__ x,
                                                const float* __restrict__ w1,
                                                const float* __restrict__ b1,
                                                const float* __restrict__ w2,
                                                const float* __restrict__ b2,
                                                float* __restrict__ out) {
    __shared__ float s_tile[3][3][264];            // [row][ch][col j], j -> w0-1+j
    __shared__ unsigned long long s_w1q[27][4];    // [tap][p] = (w1[2p][tap], w1[2p+1][tap])
    __shared__ unsigned long long s_b1q[4];        // (b1[2p], b1[2p+1])
    __shared__ float4 s_w2v[5];
    __shared__ float  s_b2[4];

    int t = threadIdx.x;
    int w0 = blockIdx.x << 8;
    int h  = blockIdx.y;
    int b  = blockIdx.z;

    // ---- weights -> smem: 27 taps x 4 o-pairs = 108 entries ----
    if (t < 108) {
        int p = t & 3, tap = t >> 2;   // tap = ch*9 + rw*3 + dj (w1 inner layout)
        s_w1q[tap][p] = pk2(w1[(2 * p) * 27 + tap], w1[(2 * p + 1) * 27 + tap]);
    } else if (t < 112) {
        int p = t - 108;
        s_b1q[p] = pk2(b1[2 * p], b1[2 * p + 1]);
    } else if (t < 117) {
        int k = t - 112;
        s_w2v[k] = make_float4(w2[3 * k], w2[3 * k + 1], w2[3 * k + 2], 0.f);
    } else if (t < 120) {
        s_b2[t - 117] = b2[t - 117];
    }

    // ---- cooperative tile load: rows h-1..h+1, 3 channels, cols w0-1..w0+256 ----
    const float* xb = x + (size_t)b * 3 * HWSZ;
#pragma unroll
    for (int rw = 0; rw < 3; rw++) {
        int hh = h + rw - 1;
        bool vh = ((unsigned)hh < 512u);
#pragma unroll
        for (int ch = 0; ch < 3; ch++) {
            const float* src = xb + (ch << 18) + (hh << 9);
#pragma unroll
            for (int jj = 0; jj < 3; jj++) {
                int j = t + (jj << 7);
                if (j < 258) {
                    int wg = w0 - 1 + j;
                    float v = (vh && (unsigned)wg < 512u) ? __ldg(src + wg) : 0.f;
                    s_tile[rw][ch][j] = v;
                }
            }
        }
    }
    __syncthreads();

    // ---- conv3x3: o-pair packed f32x2. zzA = px0 pairs, zzB = px1 pairs ----
    unsigned long long zzA[4], zzB[4];
#pragma unroll
    for (int p = 0; p < 4; p++) { zzA[p] = s_b1q[p]; zzB[p] = s_b1q[p]; }

#pragma unroll
    for (int rw = 0; rw < 3; rw++) {
#pragma unroll
        for (int ch = 0; ch < 3; ch++) {
            float2 a = *reinterpret_cast<const float2*>(&s_tile[rw][ch][2 * t]);
            float2 c = *reinterpret_cast<const float2*>(&s_tile[rw][ch][2 * t + 2]);
            // duplicated pixel operands; shared between the two pixels' taps
            unsigned long long d0 = pk2(a.x, a.x);   // px0 tap dj=0
            unsigned long long d1 = pk2(a.y, a.y);   // px0 dj=1 / px1 dj=0
            unsigned long long d2 = pk2(c.x, c.x);   // px0 dj=2 / px1 dj=1
            unsigned long long d3 = pk2(c.y, c.y);   // px1 dj=2
            int tap = ch * 9 + rw * 3;               // dj = 0 base
#pragma unroll
            for (int dj = 0; dj < 3; dj++) {
                ulonglong2 wa = *reinterpret_cast<const ulonglong2*>(&s_w1q[tap + dj][0]);
                ulonglong2 wb = *reinterpret_cast<const ulonglong2*>(&s_w1q[tap + dj][2]);
                unsigned long long pA = dj == 0 ? d0 : (dj == 1 ? d1 : d2);
                unsigned long long pB = dj == 0 ? d1 : (dj == 1 ? d2 : d3);
                zzA[0] = fma2(pA, wa.x, zzA[0]);
                zzA[1] = fma2(pA, wa.y, zzA[1]);
                zzA[2] = fma2(pA, wb.x, zzA[2]);
                zzA[3] = fma2(pA, wb.y, zzA[3]);
                zzB[0] = fma2(pB, wa.x, zzB[0]);
                zzB[1] = fma2(pB, wa.y, zzB[1]);
                zzB[2] = fma2(pB, wb.x, zzB[2]);
                zzB[3] = fma2(pB, wb.y, zzB[3]);
            }
        }
    }

    float z0[8], z1[8];
#pragma unroll
    for (int p = 0; p < 4; p++) {
        upk2(z0[2 * p], z0[2 * p + 1], zzA[p]);
        upk2(z1[2 * p], z1[2 * p + 1], zzB[p]);
    }

    // ---- sigmoid + 5 live samples + epilogue ----
    const uint4* __restrict__ colb = g_xh + ((b * 513) << 9);
    float hb = (float)h * (1.f / 511.f);
    float vb2_0 = s_b2[0], vb2_1 = s_b2[1];
    float out2 = fmaxf(s_b2[2], 0.f);
    int w = w0 + (t << 1);

    float o0[2], o1[2];
#pragma unroll
    for (int px = 0; px < 2; px++) {
        float* z = px ? z1 : z0;
        float s[8];
#pragma unroll
        for (int o = 0; o < 8; o++)
            s[o] = __fdividef(1.f, 1.f + __expf(-z[o]));
        float wb = (float)(w + px) * (1.f / 511.f);

        float a0 = 0.f, a1 = 0.f;
        samp(colb, hb + s[0], wb + s[1], s_w2v[0], a0);   // k=0
        samp(colb, hb + s[2], wb + s[3], s_w2v[1], a0);   // k=1
        samp(colb, hb + s[4], wb + s[5], s_w2v[2], a0);   // k=2
        samp(colb, hb + s[6], wb + s[7], s_w2v[3], a1);   // k=3
        samp(colb, hb,        wb,        s_w2v[4], a1);   // k=4 center
        o0[px] = fmaxf(a0 + vb2_0, 0.f);
        o1[px] = fmaxf(a1 + vb2_1, 0.f);
    }

    int po = b * 3 * HWSZ + (h << 9) + w;
    *reinterpret_cast<float2*>(out + po)            = make_float2(o0[0], o0[1]);
    *reinterpret_cast<float2*>(out + po + HWSZ)     = make_float2(o1[0], o1[1]);
    *reinterpret_cast<float2*>(out + po + 2 * HWSZ) = make_float2(out2, out2);
}

// ---------------------------------------------------------------------------
extern "C" void kernel_launch(void* const* d_in, const int* in_sizes, int n_in,
                              void* d_out, int out_size) {
    const float* x  = (const float*)d_in[0];
    const float* w1 = (const float*)d_in[1];
    const float* b1 = (const float*)d_in[2];
    const float* w2 = (const float*)d_in[3];
    const float* b2 = (const float*)d_in[4];
    float* out = (float*)d_out;

    k_prep<<<dim3(16, 16, NB), dim3(32, 8)>>>(x);
    k_seesaw<<<dim3(2, 512, NB), 128>>>(x, w1, b1, w2, b2, out);
}